// round 16
// baseline (speedup 1.0000x reference)
#include <cuda_runtime.h>
#include <cuda_fp16.h>

// ---------------------------------------------------------------------------
// Raymarcher: B=1, H=W=512, G=128, 64 steps, dt=0.02.
//
// R13: 5 requests/step (wavefront floor ~127us) but kernel 246us -> latency
// exposed (DRAM 21%: 100.6MB working set partially misses L2). R14/R16:
// LAGGED ACCUMULATION. tmpl(s) is issued at iteration s and consumed at
// iteration s+2 via a 2-slot register queue: the fetch gets ~2 iterations
// (>1400 cyc) of slack, covering even DRAM-miss latency. Legal because alpha
// compositing needs template VALUES in order, not immediately, and contrib
// is computed with the true alpha at accumulation time (stale alpha only
// affects skip heuristics, never arithmetic). 1 ray/thread (lower regs).
// Drain bookkeeping via explicit accDone counter (structurally exact).
//
// Packing (R12, validated): g_w2 16B snorm16 (wx,wy)@4 xy-corners (2 loads),
// g_w1 16B snorm16 wz@8 corners (1 load), g_t8 16B unorm8 rgbd@4 xy-corners
// (2 loads) -> 5 requests/step, volumes 100.6 MB.
//
// Discontinuity gates preserved: t0 = floor(tmin * 50.0f) * 0.02f (XLA
// lowers /dt as rcp-mul; flips floor for k in {5,10,13}); position chain in
// __fadd_rn/__fmul_rn (no FMA) so the inside test bit-matches; val *= valid
// and Sterbenz saturation keep dead/saturated lanes exactly zero-contrib.
// ---------------------------------------------------------------------------

static constexpr int GDIM = 128;
static constexpr int G2   = GDIM * GDIM;
static constexpr int G3   = GDIM * GDIM * GDIM;

__device__ int4 g_w2[G3];  // snorm16 (wx,wy) @ (x,y),(x+1,y),(x,y+1),(x+1,y+1)
__device__ int4 g_w1[G3];  // snorm16 wz @ 8 corners
__device__ int4 g_t8[G3];  // unorm8: .x=r@4xy, .y=g@4xy, .z=b@4xy, .w=d@4xy

__device__ __forceinline__ int pack2(int lo, int hi) {
    return (lo & 0xffff) | (hi << 16);
}
__device__ __forceinline__ int qs(float v) { return (int)rintf(v * 32767.0f); }
__device__ __forceinline__ int qb(float v) { return (int)rintf(v * 255.0f); }
__device__ __forceinline__ float s16lo(int v) { return (float)(short)(v & 0xffff); }
__device__ __forceinline__ float s16hi(int v) { return (float)(short)(v >> 16); }
__device__ __forceinline__ float ub(int v, int k) {
    return (float)((v >> (k * 8)) & 0xff);
}

__global__ void __launch_bounds__(256)
repack_kernel(const float* __restrict__ w, const float* __restrict__ t)
{
    int i = blockIdx.x * 256 + threadIdx.x;
    if (i >= G3) return;
    int x = i & (GDIM - 1);
    int y = (i >> 7) & (GDIM - 1);
    int z = i >> 14;
    int xp = (x < GDIM - 1) ? 1 : 0;
    int yp = (y < GDIM - 1) ? GDIM : 0;
    int zp = (z < GDIM - 1) ? G2 : 0;

    int i00 = i;
    int i10 = i + xp;
    int i01 = i + yp;
    int i11 = i + yp + xp;

    int4 e2;
    e2.x = pack2(qs(w[i00]), qs(w[i00 + G3]));
    e2.y = pack2(qs(w[i10]), qs(w[i10 + G3]));
    e2.z = pack2(qs(w[i01]), qs(w[i01 + G3]));
    e2.w = pack2(qs(w[i11]), qs(w[i11 + G3]));
    g_w2[i] = e2;

    const float* wzp = w + 2 * G3;
    int4 e1;
    e1.x = pack2(qs(wzp[i00]),      qs(wzp[i10]));
    e1.y = pack2(qs(wzp[i01]),      qs(wzp[i11]));
    e1.z = pack2(qs(wzp[i00 + zp]), qs(wzp[i10 + zp]));
    e1.w = pack2(qs(wzp[i01 + zp]), qs(wzp[i11 + zp]));
    g_w1[i] = e1;

    int4 e8;
    e8.x = qb(t[i00])           | (qb(t[i10])           << 8) |
           (qb(t[i01])          << 16) | (qb(t[i11])          << 24);
    e8.y = qb(t[i00 + G3])      | (qb(t[i10 + G3])      << 8) |
           (qb(t[i01 + G3])     << 16) | (qb(t[i11 + G3])     << 24);
    e8.z = qb(t[i00 + 2 * G3])  | (qb(t[i10 + 2 * G3])  << 8) |
           (qb(t[i01 + 2 * G3]) << 16) | (qb(t[i11 + 2 * G3]) << 24);
    e8.w = qb(t[i00 + 3 * G3])  | (qb(t[i10 + 3 * G3])  << 8) |
           (qb(t[i01 + 3 * G3]) << 16) | (qb(t[i11 + 3 * G3]) << 24);
    g_t8[i] = e8;
}

// Axis cell + weight: clamp the CELL to [0,126]; the fractional weight
// absorbs the boundary (grid_sample align_corners=True zeros padding at
// every reachable coordinate, no OOB addressing).
__device__ __forceinline__ void cellw(float p, int& c, float& wf)
{
    float u  = (p + 1.0f) * 63.5f;
    float uf = fminf(fmaxf(floorf(u), 0.0f), 126.0f);
    wf = u - uf;
    c  = (int)uf;
}

struct WFetch {
    int4 A0, A1;   // g_w2 at z0, z1
    int4 Z;        // g_w1
    float wx, wy, wz;
};
struct TFetch {
    int4 T0, T1;   // g_t8 at z0, z1
    float wx, wy, wz;
};

__device__ __forceinline__ void issueWarp(float px, float py, float pz,
                                          bool live, WFetch& f)
{
    int x0, y0, z0;
    cellw(px, x0, f.wx); cellw(py, y0, f.wy); cellw(pz, z0, f.wz);
    int base = live ? ((z0 * GDIM + y0) * GDIM + x0) : 0;
    f.A0 = __ldg(&g_w2[base]);
    f.A1 = __ldg(&g_w2[base + G2]);
    f.Z  = __ldg(&g_w1[base]);
}

__device__ __forceinline__ void issueTmpl(float px, float py, float pz,
                                          bool live, TFetch& f)
{
    int x0, y0, z0;
    cellw(px, x0, f.wx); cellw(py, y0, f.wy); cellw(pz, z0, f.wz);
    int base = live ? ((z0 * GDIM + y0) * GDIM + x0) : 0;
    f.T0 = __ldg(&g_t8[base]);
    f.T1 = __ldg(&g_t8[base + G2]);
}

__device__ __forceinline__ void combineWarp(const WFetch& f,
                                            float& ox, float& oy, float& oz)
{
    float vx = 1.0f - f.wx, vy = 1.0f - f.wy, vz = 1.0f - f.wz;
    float b00 = vy * vx, b10 = vy * f.wx, b01 = f.wy * vx, b11 = f.wy * f.wx;
    float p0 = vz * b00, p1 = vz * b10, p2 = vz * b01, p3 = vz * b11;
    float q0 = f.wz * b00, q1 = f.wz * b10, q2 = f.wz * b01, q3 = f.wz * b11;

    float sx =      s16lo(f.A0.x) * p0;
    sx = fmaf(s16lo(f.A0.y), p1, sx);
    sx = fmaf(s16lo(f.A0.z), p2, sx);
    sx = fmaf(s16lo(f.A0.w), p3, sx);
    sx = fmaf(s16lo(f.A1.x), q0, sx);
    sx = fmaf(s16lo(f.A1.y), q1, sx);
    sx = fmaf(s16lo(f.A1.z), q2, sx);
    sx = fmaf(s16lo(f.A1.w), q3, sx);

    float sy =      s16hi(f.A0.x) * p0;
    sy = fmaf(s16hi(f.A0.y), p1, sy);
    sy = fmaf(s16hi(f.A0.z), p2, sy);
    sy = fmaf(s16hi(f.A0.w), p3, sy);
    sy = fmaf(s16hi(f.A1.x), q0, sy);
    sy = fmaf(s16hi(f.A1.y), q1, sy);
    sy = fmaf(s16hi(f.A1.z), q2, sy);
    sy = fmaf(s16hi(f.A1.w), q3, sy);

    float sz =      s16lo(f.Z.x) * p0;
    sz = fmaf(s16hi(f.Z.x), p1, sz);
    sz = fmaf(s16lo(f.Z.y), p2, sz);
    sz = fmaf(s16hi(f.Z.y), p3, sz);
    sz = fmaf(s16lo(f.Z.z), q0, sz);
    sz = fmaf(s16hi(f.Z.z), q1, sz);
    sz = fmaf(s16lo(f.Z.w), q2, sz);
    sz = fmaf(s16hi(f.Z.w), q3, sz);

    const float sc = 1.0f / 32767.0f;
    ox = sx * sc; oy = sy * sc; oz = sz * sc;
}

__device__ __forceinline__ void combineTmpl(const TFetch& f,
                                            float& r, float& g, float& b, float& d)
{
    float vx = 1.0f - f.wx, vy = 1.0f - f.wy, vz = 1.0f - f.wz;
    float b00 = vy * vx, b10 = vy * f.wx, b01 = f.wy * vx, b11 = f.wy * f.wx;
    float p0 = vz * b00, p1 = vz * b10, p2 = vz * b01, p3 = vz * b11;
    float q0 = f.wz * b00, q1 = f.wz * b10, q2 = f.wz * b01, q3 = f.wz * b11;

#define TRI8(word0, word1, dst)                                   \
    do {                                                          \
        float s_ =      ub(word0, 0) * p0;                        \
        s_ = fmaf(ub(word0, 1), p1, s_);                          \
        s_ = fmaf(ub(word0, 2), p2, s_);                          \
        s_ = fmaf(ub(word0, 3), p3, s_);                          \
        s_ = fmaf(ub(word1, 0), q0, s_);                          \
        s_ = fmaf(ub(word1, 1), q1, s_);                          \
        s_ = fmaf(ub(word1, 2), q2, s_);                          \
        s_ = fmaf(ub(word1, 3), q3, s_);                          \
        dst = s_ * (1.0f / 255.0f);                               \
    } while (0)

    TRI8(f.T0.x, f.T1.x, r);
    TRI8(f.T0.y, f.T1.y, g);
    TRI8(f.T0.z, f.T1.z, b);
    TRI8(f.T0.w, f.T1.w, d);
#undef TRI8
}

__device__ __forceinline__ bool insideTest(float x, float y, float z)
{
    return (x > -1.0f) && (x < 1.0f) &&
           (y > -1.0f) && (y < 1.0f) &&
           (z > -1.0f) && (z < 1.0f);
}

__global__ void __launch_bounds__(128)
raymarch_kernel(const float* __restrict__ raypos,
                const float* __restrict__ raydir,
                const float* __restrict__ tminmax,
                const int*   __restrict__ nsteps_p,
                float* __restrict__ out, int N)
{
    int n = blockIdx.x * 128 + threadIdx.x;
    if (n >= N) return;

    const float dtf = 0.02f;

    float dx = raydir[3 * n + 0];
    float dy = raydir[3 * n + 1];
    float dz = raydir[3 * n + 2];

    // XLA lowers tmin/dt as tmin * fl(1/0.02f) == tmin * 50.0f.
    float q  = floorf(__fmul_rn(tminmax[2 * n], 50.0f));
    float t0 = __fmul_rn(q, dtf);

    float px = __fadd_rn(raypos[3 * n + 0], __fmul_rn(dx, t0));
    float py = __fadd_rn(raypos[3 * n + 1], __fmul_rn(dy, t0));
    float pz = __fadd_rn(raypos[3 * n + 2], __fmul_rn(dz, t0));

    float cx = __fmul_rn(dx, dtf);
    float cy = __fmul_rn(dy, dtf);
    float cz = __fmul_rn(dz, dtf);

    float r = 0.0f, g = 0.0f, b = 0.0f, a = 0.0f;
    int ns = nsteps_p ? nsteps_p[0] : 64;

    bool inside = insideTest(px, py, pz);
    WFetch wf;
    issueWarp(px, py, pz, inside, wf);      // warp fetch for step 0

    // Two-slot template queue: tmpl(s) issued at iter s, consumed at s+2.
    TFetch tq[2];
    float  vq[2];

#define ACCUM_SLOT(SLOT)                                          \
    do {                                                          \
        float vr_, vg_, vb_, vd_;                                 \
        combineTmpl(tq[(SLOT)], vr_, vg_, vb_, vd_);              \
        float valid_ = vq[(SLOT)];                                \
        vr_ *= valid_; vg_ *= valid_; vb_ *= valid_; vd_ *= valid_; \
        float av_ = __fadd_rn(a, __fmul_rn(vd_, dtf));            \
        float contrib_ = __fadd_rn(fminf(av_, 1.0f), -a);         \
        r = fmaf(vr_, contrib_, r);                               \
        g = fmaf(vg_, contrib_, g);                               \
        b = fmaf(vb_, contrib_, b);                               \
        a = __fadd_rn(a, contrib_);                               \
    } while (0)

    int s = 0;
    int accDone = 0;   // number of queued steps already accumulated
    for (; s < ns; ++s) {
        int slot = s & 1;

        // Accumulate step s-2 (same slot parity). Sequential in s, so the
        // alpha compositing order is identical to the reference.
        if (s >= 2) {
            ACCUM_SLOT(slot);
            accDone = s - 1;     // steps 0..s-2 consumed
        }

        // Break/live heuristics on (possibly 2-step-stale) alpha:
        // conservative only — saturated/dead lanes contribute exact zeros.
        bool done = (!inside) || (a >= 1.0f);
        unsigned m = __activemask();
        if (__all_sync(m, done)) break;

        // Issue tmpl(s) from warp(s); enqueue.
        vq[slot] = inside ? 1.0f : 0.0f;
        float sx, sy, sz;
        combineWarp(wf, sx, sy, sz);
        issueTmpl(sx, sy, sz, !done, tq[slot]);

        // Advance position (exact chain) and issue warp(s+1).
        float npx = __fadd_rn(px, cx);
        float npy = __fadd_rn(py, cy);
        float npz = __fadd_rn(pz, cz);
        bool nin  = insideTest(npx, npy, npz);
        issueWarp(npx, npy, npz, nin, wf);
        px = npx; py = npy; pz = npz;
        inside = nin;
    }

    // Drain exactly the issued-but-unconsumed steps [accDone, s), in order.
    for (int k = accDone; k < s; ++k) {
        ACCUM_SLOT(k & 1);
    }
#undef ACCUM_SLOT

    out[0 * N + n] = r;
    out[1 * N + n] = g;
    out[2 * N + n] = b;
    out[3 * N + n] = a;
}

extern "C" void kernel_launch(void* const* d_in, const int* in_sizes, int n_in,
                              void* d_out, int out_size)
{
    const float* raypos = (const float*)d_in[0];
    const float* raydir = (const float*)d_in[1];
    const float* tmm    = (const float*)d_in[2];
    const float* warp   = (const float*)d_in[3];
    const float* tmpl   = (const float*)d_in[4];
    const int*   nsteps = (n_in > 5) ? (const int*)d_in[5] : nullptr;

    int N = in_sizes[0] / 3;

    repack_kernel<<<(G3 + 255) / 256, 256>>>(warp, tmpl);
    raymarch_kernel<<<(N + 127) / 128, 128>>>(raypos, raydir, tmm, nsteps,
                                              (float*)d_out, N);
}

// round 17
// speedup vs baseline: 1.0922x; 1.0922x over previous
#include <cuda_runtime.h>
#include <cuda_fp16.h>

// ---------------------------------------------------------------------------
// Raymarcher: B=1, H=W=512, G=128, 64 steps, dt=0.02.
//
// R16 post-mortem: lagged accumulation REGRESSED because ptxas (default
// occupancy heuristic, plain __launch_bounds__(128)) chose 48 regs and
// SPILLED the 2-slot template queue to local memory -> DRAM 35%, alu up.
// R17 = identical structure with __launch_bounds__(128, 6): reg budget 85,
// queue stays in registers, occupancy capped at 24 warps/SM (R13-level,
// which sustains wavefront throughput).
//
// LAGGED ACCUMULATION: tmpl(s) issued at iter s, consumed at iter s+2 via a
// 2-slot register queue -> the fetch gets ~2 iterations (>1400 cyc) of
// slack, covering DRAM-miss latency (100.6MB working set partially misses
// L2). Legal: alpha compositing needs template VALUES in order, not
// immediately; contrib is computed with the true alpha at accumulation
// time (stale alpha only affects skip heuristics, never arithmetic).
//
// Packing (R12, validated): g_w2 16B snorm16 (wx,wy)@4 xy-corners (2 loads),
// g_w1 16B snorm16 wz@8 corners (1 load), g_t8 16B unorm8 rgbd@4 xy-corners
// (2 loads) -> 5 requests/step.
//
// Discontinuity gates preserved: t0 = floor(tmin * 50.0f) * 0.02f (XLA
// lowers /dt as rcp-mul; flips floor for k in {5,10,13}); position chain in
// __fadd_rn/__fmul_rn (no FMA) so the inside test bit-matches; val *= valid
// and Sterbenz saturation keep dead/saturated lanes exactly zero-contrib.
// ---------------------------------------------------------------------------

static constexpr int GDIM = 128;
static constexpr int G2   = GDIM * GDIM;
static constexpr int G3   = GDIM * GDIM * GDIM;

__device__ int4 g_w2[G3];  // snorm16 (wx,wy) @ (x,y),(x+1,y),(x,y+1),(x+1,y+1)
__device__ int4 g_w1[G3];  // snorm16 wz @ 8 corners
__device__ int4 g_t8[G3];  // unorm8: .x=r@4xy, .y=g@4xy, .z=b@4xy, .w=d@4xy

__device__ __forceinline__ int pack2(int lo, int hi) {
    return (lo & 0xffff) | (hi << 16);
}
__device__ __forceinline__ int qs(float v) { return (int)rintf(v * 32767.0f); }
__device__ __forceinline__ int qb(float v) { return (int)rintf(v * 255.0f); }
__device__ __forceinline__ float s16lo(int v) { return (float)(short)(v & 0xffff); }
__device__ __forceinline__ float s16hi(int v) { return (float)(short)(v >> 16); }
__device__ __forceinline__ float ub(int v, int k) {
    return (float)((v >> (k * 8)) & 0xff);
}

__global__ void __launch_bounds__(256)
repack_kernel(const float* __restrict__ w, const float* __restrict__ t)
{
    int i = blockIdx.x * 256 + threadIdx.x;
    if (i >= G3) return;
    int x = i & (GDIM - 1);
    int y = (i >> 7) & (GDIM - 1);
    int z = i >> 14;
    int xp = (x < GDIM - 1) ? 1 : 0;
    int yp = (y < GDIM - 1) ? GDIM : 0;
    int zp = (z < GDIM - 1) ? G2 : 0;

    int i00 = i;
    int i10 = i + xp;
    int i01 = i + yp;
    int i11 = i + yp + xp;

    int4 e2;
    e2.x = pack2(qs(w[i00]), qs(w[i00 + G3]));
    e2.y = pack2(qs(w[i10]), qs(w[i10 + G3]));
    e2.z = pack2(qs(w[i01]), qs(w[i01 + G3]));
    e2.w = pack2(qs(w[i11]), qs(w[i11 + G3]));
    g_w2[i] = e2;

    const float* wzp = w + 2 * G3;
    int4 e1;
    e1.x = pack2(qs(wzp[i00]),      qs(wzp[i10]));
    e1.y = pack2(qs(wzp[i01]),      qs(wzp[i11]));
    e1.z = pack2(qs(wzp[i00 + zp]), qs(wzp[i10 + zp]));
    e1.w = pack2(qs(wzp[i01 + zp]), qs(wzp[i11 + zp]));
    g_w1[i] = e1;

    int4 e8;
    e8.x = qb(t[i00])           | (qb(t[i10])           << 8) |
           (qb(t[i01])          << 16) | (qb(t[i11])          << 24);
    e8.y = qb(t[i00 + G3])      | (qb(t[i10 + G3])      << 8) |
           (qb(t[i01 + G3])     << 16) | (qb(t[i11 + G3])     << 24);
    e8.z = qb(t[i00 + 2 * G3])  | (qb(t[i10 + 2 * G3])  << 8) |
           (qb(t[i01 + 2 * G3]) << 16) | (qb(t[i11 + 2 * G3]) << 24);
    e8.w = qb(t[i00 + 3 * G3])  | (qb(t[i10 + 3 * G3])  << 8) |
           (qb(t[i01 + 3 * G3]) << 16) | (qb(t[i11 + 3 * G3]) << 24);
    g_t8[i] = e8;
}

// Axis cell + weight: clamp the CELL to [0,126]; the fractional weight
// absorbs the boundary (grid_sample align_corners=True zeros padding at
// every reachable coordinate, no OOB addressing).
__device__ __forceinline__ void cellw(float p, int& c, float& wf)
{
    float u  = (p + 1.0f) * 63.5f;
    float uf = fminf(fmaxf(floorf(u), 0.0f), 126.0f);
    wf = u - uf;
    c  = (int)uf;
}

struct WFetch {
    int4 A0, A1;   // g_w2 at z0, z1
    int4 Z;        // g_w1
    float wx, wy, wz;
};
struct TFetch {
    int4 T0, T1;   // g_t8 at z0, z1
    float wx, wy, wz;
};

__device__ __forceinline__ void issueWarp(float px, float py, float pz,
                                          bool live, WFetch& f)
{
    int x0, y0, z0;
    cellw(px, x0, f.wx); cellw(py, y0, f.wy); cellw(pz, z0, f.wz);
    int base = live ? ((z0 * GDIM + y0) * GDIM + x0) : 0;
    f.A0 = __ldg(&g_w2[base]);
    f.A1 = __ldg(&g_w2[base + G2]);
    f.Z  = __ldg(&g_w1[base]);
}

__device__ __forceinline__ void issueTmpl(float px, float py, float pz,
                                          bool live, TFetch& f)
{
    int x0, y0, z0;
    cellw(px, x0, f.wx); cellw(py, y0, f.wy); cellw(pz, z0, f.wz);
    int base = live ? ((z0 * GDIM + y0) * GDIM + x0) : 0;
    f.T0 = __ldg(&g_t8[base]);
    f.T1 = __ldg(&g_t8[base + G2]);
}

__device__ __forceinline__ void combineWarp(const WFetch& f,
                                            float& ox, float& oy, float& oz)
{
    float vx = 1.0f - f.wx, vy = 1.0f - f.wy, vz = 1.0f - f.wz;
    float b00 = vy * vx, b10 = vy * f.wx, b01 = f.wy * vx, b11 = f.wy * f.wx;
    float p0 = vz * b00, p1 = vz * b10, p2 = vz * b01, p3 = vz * b11;
    float q0 = f.wz * b00, q1 = f.wz * b10, q2 = f.wz * b01, q3 = f.wz * b11;

    float sx =      s16lo(f.A0.x) * p0;
    sx = fmaf(s16lo(f.A0.y), p1, sx);
    sx = fmaf(s16lo(f.A0.z), p2, sx);
    sx = fmaf(s16lo(f.A0.w), p3, sx);
    sx = fmaf(s16lo(f.A1.x), q0, sx);
    sx = fmaf(s16lo(f.A1.y), q1, sx);
    sx = fmaf(s16lo(f.A1.z), q2, sx);
    sx = fmaf(s16lo(f.A1.w), q3, sx);

    float sy =      s16hi(f.A0.x) * p0;
    sy = fmaf(s16hi(f.A0.y), p1, sy);
    sy = fmaf(s16hi(f.A0.z), p2, sy);
    sy = fmaf(s16hi(f.A0.w), p3, sy);
    sy = fmaf(s16hi(f.A1.x), q0, sy);
    sy = fmaf(s16hi(f.A1.y), q1, sy);
    sy = fmaf(s16hi(f.A1.z), q2, sy);
    sy = fmaf(s16hi(f.A1.w), q3, sy);

    float sz =      s16lo(f.Z.x) * p0;
    sz = fmaf(s16hi(f.Z.x), p1, sz);
    sz = fmaf(s16lo(f.Z.y), p2, sz);
    sz = fmaf(s16hi(f.Z.y), p3, sz);
    sz = fmaf(s16lo(f.Z.z), q0, sz);
    sz = fmaf(s16hi(f.Z.z), q1, sz);
    sz = fmaf(s16lo(f.Z.w), q2, sz);
    sz = fmaf(s16hi(f.Z.w), q3, sz);

    const float sc = 1.0f / 32767.0f;
    ox = sx * sc; oy = sy * sc; oz = sz * sc;
}

__device__ __forceinline__ void combineTmpl(const TFetch& f,
                                            float& r, float& g, float& b, float& d)
{
    float vx = 1.0f - f.wx, vy = 1.0f - f.wy, vz = 1.0f - f.wz;
    float b00 = vy * vx, b10 = vy * f.wx, b01 = f.wy * vx, b11 = f.wy * f.wx;
    float p0 = vz * b00, p1 = vz * b10, p2 = vz * b01, p3 = vz * b11;
    float q0 = f.wz * b00, q1 = f.wz * b10, q2 = f.wz * b01, q3 = f.wz * b11;

#define TRI8(word0, word1, dst)                                   \
    do {                                                          \
        float s_ =      ub(word0, 0) * p0;                        \
        s_ = fmaf(ub(word0, 1), p1, s_);                          \
        s_ = fmaf(ub(word0, 2), p2, s_);                          \
        s_ = fmaf(ub(word0, 3), p3, s_);                          \
        s_ = fmaf(ub(word1, 0), q0, s_);                          \
        s_ = fmaf(ub(word1, 1), q1, s_);                          \
        s_ = fmaf(ub(word1, 2), q2, s_);                          \
        s_ = fmaf(ub(word1, 3), q3, s_);                          \
        dst = s_ * (1.0f / 255.0f);                               \
    } while (0)

    TRI8(f.T0.x, f.T1.x, r);
    TRI8(f.T0.y, f.T1.y, g);
    TRI8(f.T0.z, f.T1.z, b);
    TRI8(f.T0.w, f.T1.w, d);
#undef TRI8
}

__device__ __forceinline__ bool insideTest(float x, float y, float z)
{
    return (x > -1.0f) && (x < 1.0f) &&
           (y > -1.0f) && (y < 1.0f) &&
           (z > -1.0f) && (z < 1.0f);
}

// min-blocks 6 -> reg budget 85: forbids ptxas's 48-reg spill choice (R16's
// regression root cause) while keeping >= 24 warps/SM if regs stay <= 85.
__global__ void __launch_bounds__(128, 6)
raymarch_kernel(const float* __restrict__ raypos,
                const float* __restrict__ raydir,
                const float* __restrict__ tminmax,
                const int*   __restrict__ nsteps_p,
                float* __restrict__ out, int N)
{
    int n = blockIdx.x * 128 + threadIdx.x;
    if (n >= N) return;

    const float dtf = 0.02f;

    float dx = raydir[3 * n + 0];
    float dy = raydir[3 * n + 1];
    float dz = raydir[3 * n + 2];

    // XLA lowers tmin/dt as tmin * fl(1/0.02f) == tmin * 50.0f.
    float q  = floorf(__fmul_rn(tminmax[2 * n], 50.0f));
    float t0 = __fmul_rn(q, dtf);

    float px = __fadd_rn(raypos[3 * n + 0], __fmul_rn(dx, t0));
    float py = __fadd_rn(raypos[3 * n + 1], __fmul_rn(dy, t0));
    float pz = __fadd_rn(raypos[3 * n + 2], __fmul_rn(dz, t0));

    float cx = __fmul_rn(dx, dtf);
    float cy = __fmul_rn(dy, dtf);
    float cz = __fmul_rn(dz, dtf);

    float r = 0.0f, g = 0.0f, b = 0.0f, a = 0.0f;
    int ns = nsteps_p ? nsteps_p[0] : 64;

    bool inside = insideTest(px, py, pz);
    WFetch wf;
    issueWarp(px, py, pz, inside, wf);      // warp fetch for step 0

    // Two-slot template queue: tmpl(s) issued at iter s, consumed at s+2.
    TFetch tq[2];
    float  vq[2];

#define ACCUM_SLOT(SLOT)                                          \
    do {                                                          \
        float vr_, vg_, vb_, vd_;                                 \
        combineTmpl(tq[(SLOT)], vr_, vg_, vb_, vd_);              \
        float valid_ = vq[(SLOT)];                                \
        vr_ *= valid_; vg_ *= valid_; vb_ *= valid_; vd_ *= valid_; \
        float av_ = __fadd_rn(a, __fmul_rn(vd_, dtf));            \
        float contrib_ = __fadd_rn(fminf(av_, 1.0f), -a);         \
        r = fmaf(vr_, contrib_, r);                               \
        g = fmaf(vg_, contrib_, g);                               \
        b = fmaf(vb_, contrib_, b);                               \
        a = __fadd_rn(a, contrib_);                               \
    } while (0)

    int s = 0;
    int accDone = 0;   // number of queued steps already accumulated
    for (; s < ns; ++s) {
        int slot = s & 1;

        // Accumulate step s-2 (same slot parity). Sequential in s, so the
        // alpha compositing order is identical to the reference.
        if (s >= 2) {
            ACCUM_SLOT(slot);
            accDone = s - 1;     // steps 0..s-2 consumed
        }

        // Break/live heuristics on (possibly 2-step-stale) alpha:
        // conservative only — saturated/dead lanes contribute exact zeros.
        bool done = (!inside) || (a >= 1.0f);
        unsigned m = __activemask();
        if (__all_sync(m, done)) break;

        // Issue tmpl(s) from warp(s); enqueue.
        vq[slot] = inside ? 1.0f : 0.0f;
        float sx, sy, sz;
        combineWarp(wf, sx, sy, sz);
        issueTmpl(sx, sy, sz, !done, tq[slot]);

        // Advance position (exact chain) and issue warp(s+1).
        float npx = __fadd_rn(px, cx);
        float npy = __fadd_rn(py, cy);
        float npz = __fadd_rn(pz, cz);
        bool nin  = insideTest(npx, npy, npz);
        issueWarp(npx, npy, npz, nin, wf);
        px = npx; py = npy; pz = npz;
        inside = nin;
    }

    // Drain exactly the issued-but-unconsumed steps [accDone, s), in order.
    for (int k = accDone; k < s; ++k) {
        ACCUM_SLOT(k & 1);
    }
#undef ACCUM_SLOT

    out[0 * N + n] = r;
    out[1 * N + n] = g;
    out[2 * N + n] = b;
    out[3 * N + n] = a;
}

extern "C" void kernel_launch(void* const* d_in, const int* in_sizes, int n_in,
                              void* d_out, int out_size)
{
    const float* raypos = (const float*)d_in[0];
    const float* raydir = (const float*)d_in[1];
    const float* tmm    = (const float*)d_in[2];
    const float* warp   = (const float*)d_in[3];
    const float* tmpl   = (const float*)d_in[4];
    const int*   nsteps = (n_in > 5) ? (const int*)d_in[5] : nullptr;

    int N = in_sizes[0] / 3;

    repack_kernel<<<(G3 + 255) / 256, 256>>>(warp, tmpl);
    raymarch_kernel<<<(N + 127) / 128, 128>>>(raypos, raydir, tmm, nsteps,
                                              (float*)d_out, N);
}